// round 14
// baseline (speedup 1.0000x reference)
#include <cuda_runtime.h>
#include <cuda_bf16.h>
#include <cstdint>

#define BATCH 2
#define CH 64
#define HW 4096   // 64*64
#define NSP 2     // KV splits

typedef unsigned long long u64;

__device__ __forceinline__ u64 pk2(float lo, float hi) {
    u64 r; asm("mov.b64 %0,{%1,%2};" : "=l"(r) : "f"(lo), "f"(hi)); return r;
}
__device__ __forceinline__ void upk2(u64 v, float& lo, float& hi) {
    asm("mov.b64 {%0,%1},%2;" : "=f"(lo), "=f"(hi) : "l"(v));
}
__device__ __forceinline__ u64 ffma2(u64 a, u64 b, u64 c) {
    u64 d; asm("fma.rn.f32x2 %0,%1,%2,%3;" : "=l"(d) : "l"(a), "l"(b), "l"(c)); return d;
}

// ---------------- scratch ----------------
__device__ float g_scale[4 * CH];
__device__ float g_xg[BATCH * CH * HW];
__device__ float g_gg[BATCH * CH * HW];
__device__ float g_xq[BATCH * CH * HW];
__device__ float g_gq[BATCH * CH * HW];
__device__ float g_gout[BATCH * CH * HW];
__device__ float g_outb[BATCH * CH * HW];
__device__ float g_t1[BATCH * CH * HW];
__device__ float g_sc[BATCH * CH * HW];
__device__ __nv_bfloat16 g_bkh[2 * BATCH * CH * HW];
__device__ __nv_bfloat16 g_bkl[2 * BATCH * CH * HW];
__device__ __nv_bfloat16 g_bvh[BATCH * CH * HW];
__device__ __nv_bfloat16 g_bvl[BATCH * CH * HW];
// split-KV partials
__device__ float g_pO[2 * BATCH * NSP * CH * HW];
__device__ float g_pm[2 * BATCH * NSP * HW];
__device__ float g_pl[2 * BATCH * NSP * HW];

#define BUF_XG 0
#define BUF_GG 1
#define BUF_OUT 2
#define BUF_T1 3

#define BUF_SC 5
#define BUF_OT1 6

__device__ __forceinline__ float* pick_in(int w) {
    switch (w) {
        case BUF_XG: return g_xg;
        case BUF_GG: return g_gg;
        case BUF_OUT: return g_outb;
        default:     return g_t1;
    }
}
__device__ __forceinline__ float* pick_out(int w) {
    switch (w) {
        case BUF_SC: return g_sc;
        default:     return g_t1;
    }
}

// ================= helpers =================
__device__ __forceinline__ uint32_t su32(const void* p) {
    uint32_t a;
    asm("{ .reg .u64 t; cvta.to.shared.u64 t, %1; cvt.u32.u64 %0, t; }" : "=r"(a) : "l"(p));
    return a;
}
__device__ __forceinline__ void mma_bf16(float* d, const uint32_t* a, uint32_t b0, uint32_t b1) {
    asm volatile(
        "mma.sync.aligned.m16n8k16.row.col.f32.bf16.bf16.f32 "
        "{%0,%1,%2,%3}, {%4,%5,%6,%7}, {%8,%9}, {%0,%1,%2,%3};"
        : "+f"(d[0]), "+f"(d[1]), "+f"(d[2]), "+f"(d[3])
        : "r"(a[0]), "r"(a[1]), "r"(a[2]), "r"(a[3]), "r"(b0), "r"(b1));
}
__device__ __forceinline__ void ldsm4(uint32_t* r, uint32_t addr) {
    asm volatile("ldmatrix.sync.aligned.m8n8.x4.shared.b16 {%0,%1,%2,%3}, [%4];"
                 : "=r"(r[0]), "=r"(r[1]), "=r"(r[2]), "=r"(r[3]) : "r"(addr));
}
__device__ __forceinline__ void ldsm4t(uint32_t* r, uint32_t addr) {
    asm volatile("ldmatrix.sync.aligned.m8n8.x4.trans.shared.b16 {%0,%1,%2,%3}, [%4];"
                 : "=r"(r[0]), "=r"(r[1]), "=r"(r[2]), "=r"(r[3]) : "r"(addr));
}
__device__ __forceinline__ uint32_t cvt_bf2(float lo, float hi) {
    uint32_t r;
    asm("cvt.rn.bf16x2.f32 %0, %1, %2;" : "=r"(r) : "f"(hi), "f"(lo));
    return r;
}
__device__ __forceinline__ void split2(float a, float b, uint32_t& hw, uint32_t& lw) {
    uint32_t h = cvt_bf2(a, b);
    float ra = a - __uint_as_float(h << 16);
    float rb = b - __uint_as_float(h & 0xFFFF0000u);
    hw = h;
    lw = cvt_bf2(ra, rb);
}
__device__ __forceinline__ void wrb(__nv_bfloat16* H, __nv_bfloat16* L, int idx, float v) {
    __nv_bfloat16 h = __float2bfloat16_rn(v);
    H[idx] = h;
    L[idx] = __float2bfloat16_rn(v - __bfloat162float(h));
}
__device__ __forceinline__ void cpa16(uint32_t dst, const void* src) {
    asm volatile("cp.async.cg.shared.global [%0], [%1], 16;" :: "r"(dst), "l"(src) : "memory");
}
#define CPA_COMMIT() asm volatile("cp.async.commit_group;" ::: "memory")
#define CPA_WAIT1()  asm volatile("cp.async.wait_group 1;" ::: "memory")
#define CPA_WAIT0()  asm volatile("cp.async.wait_group 0;" ::: "memory")

// ---------------- 1. channel attention scalars ----------------
__global__ void kstats(const float* __restrict__ x, const float* __restrict__ g,
                       const float* __restrict__ lw, const float* __restrict__ lb) {
    int idx = blockIdx.x;
    int t = idx >> 7, b = (idx >> 6) & 1, c = idx & 63;
    const float* in = (t ? g : x) + (b * CH + c) * HW;
    float s = 0.f;
    for (int i = threadIdx.x; i < HW; i += 256) s += in[i];
    __shared__ float red[8];
    #pragma unroll
    for (int o = 16; o > 0; o >>= 1) s += __shfl_xor_sync(0xffffffffu, s, o);
    if ((threadIdx.x & 31) == 0) red[threadIdx.x >> 5] = s;
    __syncthreads();
    if (threadIdx.x == 0) {
        float tot = 0.f;
        #pragma unroll
        for (int i = 0; i < 8; i++) tot += red[i];
        float p = tot * (1.0f / (float)HW);
        float W = lw[0], B = lb[0];
        float h = p * W + B;
        h = h > 0.f ? h : 0.1f * h;
        float z = h * W + B;
        g_scale[idx] = 1.f / (1.f + expf(-z));
    }
}

// ---------------- 2. gated coord conv: 4 oc, 2 px/thread, 512 CTAs ----------------
__global__ void __launch_bounds__(256) kgated(const float* __restrict__ xin,
                                              const float* __restrict__ gin,
                                              const float* __restrict__ cw) {
    int z = blockIdx.z;
    int t = z >> 1, b = z & 1;
    const float* in = (t ? gin : xin) + b * CH * HW;
    float* out = (t ? g_gg : g_xg) + b * CH * HW;
    int ocg = blockIdx.y;

    __shared__ float ws[4 * 66 * 9];
    for (int i = threadIdx.x; i < 4 * 594; i += 256) {
        int o = i / 594, r = i % 594;
        ws[o * 594 + r] = cw[(ocg * 4 + o) * 594 + r];
    }
    __syncthreads();

    int p = blockIdx.x * 512 + threadIdx.x * 2;
    int row = p >> 6, col0 = p & 63;
    float acc[4][2];
    #pragma unroll
    for (int o = 0; o < 4; o++) { acc[o][0] = 0.f; acc[o][1] = 0.f; }

    for (int ic = 0; ic < 64; ic++) {
        const float* ch = in + ic * HW;
        #pragma unroll
        for (int kh = 0; kh < 3; kh++) {
            int hh = row + kh - 1;
            if ((unsigned)hh >= 64u) continue;
            float v[4];
            #pragma unroll
            for (int u = 0; u < 4; u++) {
                int cc = col0 - 1 + u;
                v[u] = ((unsigned)cc < 64u) ? ch[hh * 64 + cc] : 0.f;
            }
            #pragma unroll
            for (int o = 0; o < 4; o++) {
                const float* wr = &ws[o * 594 + ic * 9 + kh * 3];
                #pragma unroll
                for (int kw = 0; kw < 3; kw++) {
                    float wv = wr[kw];
                    acc[o][0] += wv * v[kw + 0];
                    acc[o][1] += wv * v[kw + 1];
                }
            }
        }
    }
    #pragma unroll
    for (int ic = 64; ic < 66; ic++) {
        #pragma unroll
        for (int kh = 0; kh < 3; kh++) {
            int hh = row + kh - 1;
            if ((unsigned)hh >= 64u) continue;
            float yyv = (float)hh * (2.f / 63.f) - 1.f;
            float v[4];
            #pragma unroll
            for (int u = 0; u < 4; u++) {
                int cc = col0 - 1 + u;
                float val = 0.f;
                if ((unsigned)cc < 64u)
                    val = (ic == 64) ? ((float)cc * (2.f / 63.f) - 1.f) : yyv;
                v[u] = val;
            }
            #pragma unroll
            for (int o = 0; o < 4; o++) {
                const float* wr = &ws[o * 594 + ic * 9 + kh * 3];
                #pragma unroll
                for (int kw = 0; kw < 3; kw++) {
                    float wv = wr[kw];
                    acc[o][0] += wv * v[kw + 0];
                    acc[o][1] += wv * v[kw + 1];
                }
            }
        }
    }

    #pragma unroll
    for (int o = 0; o < 4; o++) {
        int oc = ocg * 4 + o;
        float s = g_scale[z * CH + oc];
        *(float2*)(out + oc * HW + p) = make_float2(s * acc[o][0], s * acc[o][1]);
    }
}

// ---------------- 3. fused QKV projections; K/V written as bf16 hi/lo ----------------
__global__ void __launch_bounds__(128) kproj(
    const float* __restrict__ xq_w, const float* __restrict__ xq_b,
    const float* __restrict__ xk_w, const float* __restrict__ xk_b,
    const float* __restrict__ xv_w, const float* __restrict__ xv_b,
    const float* __restrict__ gq_w, const float* __restrict__ gq_b,
    const float* __restrict__ gk_w, const float* __restrict__ gk_b) {
    __shared__ float si[64 * 128];
    __shared__ float swt[3 * 512];
    __shared__ float sb2[3 * 8];

    int z = blockIdx.z;
    int side = z >> 1, b = z & 1;
    int og = blockIdx.y;
    int n0 = blockIdx.x * 128;
    int tid = threadIdx.x;

    const float* in = (side ? g_gg : g_xg) + b * CH * HW;
    const float* ws[3];
    const float* bs[3];
    int nset;
    if (side == 0) {
        ws[0] = xq_w; ws[1] = xk_w; ws[2] = xv_w;
        bs[0] = xq_b; bs[1] = xk_b; bs[2] = xv_b;
        nset = 3;
    } else {
        ws[0] = gq_w; ws[1] = gk_w; ws[2] = gk_w;
        bs[0] = gq_b; bs[1] = gk_b; bs[2] = gk_b;
        nset = 2;
    }

    for (int i = tid; i < 2048; i += 128) {
        int c = i >> 5, p4 = (i & 31) * 4;
        *(float4*)(si + c * 128 + p4) = *(const float4*)(in + c * HW + n0 + p4);
    }
    for (int s = 0; s < nset; s++) {
        for (int i = tid; i < 512; i += 128) {
            int c = i >> 3, o = i & 7;
            swt[s * 512 + c * 8 + o] = ws[s][(og * 8 + o) * 64 + c];
        }
        if (tid < 8) sb2[s * 8 + tid] = bs[s][og * 8 + tid];
    }
    __syncthreads();

    u64 acc[3][4];
    #pragma unroll
    for (int s = 0; s < 3; s++)
        #pragma unroll
        for (int k = 0; k < 4; k++)
            acc[s][k] = pk2(sb2[s * 8 + 2 * k], sb2[s * 8 + 2 * k + 1]);

    if (side == 0) {
        for (int c = 0; c < 64; c++) {
            float iv = si[c * 128 + tid];
            u64 ivp = pk2(iv, iv);
            #pragma unroll
            for (int s = 0; s < 3; s++) {
                ulonglong2 wa = *(const ulonglong2*)(swt + s * 512 + c * 8);
                ulonglong2 wb = *(const ulonglong2*)(swt + s * 512 + c * 8 + 4);
                acc[s][0] = ffma2(ivp, wa.x, acc[s][0]);
                acc[s][1] = ffma2(ivp, wa.y, acc[s][1]);
                acc[s][2] = ffma2(ivp, wb.x, acc[s][2]);
                acc[s][3] = ffma2(ivp, wb.y, acc[s][3]);
            }
        }
    } else {
        for (int c = 0; c < 64; c++) {
            float iv = si[c * 128 + tid];
            u64 ivp = pk2(iv, iv);
            #pragma unroll
            for (int s = 0; s < 2; s++) {
                ulonglong2 wa = *(const ulonglong2*)(swt + s * 512 + c * 8);
                ulonglong2 wb = *(const ulonglong2*)(swt + s * 512 + c * 8 + 4);
                acc[s][0] = ffma2(ivp, wa.x, acc[s][0]);
                acc[s][1] = ffma2(ivp, wa.y, acc[s][1]);
                acc[s][2] = ffma2(ivp, wb.x, acc[s][2]);
                acc[s][3] = ffma2(ivp, wb.y, acc[s][3]);
            }
        }
    }

    float* qdst = side ? g_gq : g_xq;
    __nv_bfloat16* KhD = g_bkh + (long)side * BATCH * CH * HW;
    __nv_bfloat16* KlD = g_bkl + (long)side * BATCH * CH * HW;
    #pragma unroll
    for (int k = 0; k < 4; k++) {
        int i0 = (b * CH + og * 8 + 2 * k) * HW + n0 + tid;
        float lo, hi;
        upk2(acc[0][k], lo, hi);
        qdst[i0] = lo; qdst[i0 + HW] = hi;
        upk2(acc[1][k], lo, hi);
        wrb(KhD, KlD, i0, lo); wrb(KhD, KlD, i0 + HW, hi);
        if (side == 0) {
            upk2(acc[2][k], lo, hi);
            wrb(g_bvh, g_bvl, i0, lo); wrb(g_bvh, g_bvl, i0 + HW, hi);
        }
    }
}

// ---------------- 4. flash attention: split-KV, 256 threads, double-buffered, 1 wave ----------------
__global__ void __launch_bounds__(256, 2) kattn() {
    extern __shared__ __align__(16) uint8_t dyn[];

    const int tid = threadIdx.x;
    const int lane = tid & 31, wid = tid >> 5;
    const int tg = lane & 3, g = lane >> 2;
    const int b = blockIdx.y, kind = blockIdx.z;
    const int nt = blockIdx.x >> 1, sp = blockIdx.x & 1;
    const int n0 = nt * 128;
    const int kt0 = sp * 32;
    const float* Qp = (kind ? g_gq : g_xq) + b * CH * HW;
    const __nv_bfloat16* Kh = g_bkh + ((long)kind * BATCH + b) * CH * HW;
    const __nv_bfloat16* Kl = g_bkl + ((long)kind * BATCH + b) * CH * HW;
    const __nv_bfloat16* Vh = g_bvh + (long)b * CH * HW;
    const __nv_bfloat16* Vl = g_bvl + (long)b * CH * HW;

    const uint32_t sb = su32(dyn);

    for (int idx = tid; idx < 8192; idx += 256) {
        int i = idx & 127, c = idx >> 7;
        float a = Qp[c * HW + n0 + i];
        __nv_bfloat16 h = __float2bfloat16_rn(a);
        uint32_t off = (uint32_t)(i * 128 + ((((c >> 3) ^ (i & 7))) << 4) + (c & 7) * 2);
        *(__nv_bfloat16*)(dyn + off) = h;
        *(__nv_bfloat16*)(dyn + 16384 + off) = __float2bfloat16_rn(a - __bfloat162float(h));
    }
    __syncthreads();

    const int rl = lane & 15, hi_half = lane >> 4, r7 = rl & 7;
    uint32_t qh[4][4], ql[4][4];
    #pragma unroll
    for (int kc = 0; kc < 4; kc++) {
        uint32_t off = (uint32_t)((16 * wid + rl) * 128 + (((kc * 2 + hi_half) ^ r7) << 4));
        ldsm4(qh[kc], sb + off);
        ldsm4(ql[kc], sb + 16384 + off);
    }
    __syncthreads();

    float oacc[8][4];
    #pragma unroll
    for (int cb = 0; cb < 8; cb++) {
        oacc[cb][0] = 0.f; oacc[cb][1] = 0.f; oacc[cb][2] = 0.f; oacc[cb][3] = 0.f;
    }
    float mrow0 = -1e30f, mrow1 = -1e30f, lrow0 = 0.f, lrow1 = 0.f;

    const int vrow = ((lane >> 4) << 3) + (lane & 7);
    const int vch = (lane >> 3) & 1;
    const int v7 = lane & 7;

    {
        int m0 = kt0 * 64;
        #pragma unroll
        for (int u = 0; u < 2; u++) {
            int i = tid + u * 256;
            int row = i >> 3, ch = i & 7;
            uint32_t dst = sb + row * 128 + (((ch ^ (row & 7))) << 4);
            long go = (long)row * HW + m0 + ch * 8;
            cpa16(dst,          Kh + go);
            cpa16(dst + 8192,   Kl + go);
            cpa16(dst + 16384,  Vh + go);
            cpa16(dst + 24576,  Vl + go);
        }
        CPA_COMMIT();
    }

    for (int kt = 0; kt < 32; kt++) {
        const uint32_t bufc = sb + (uint32_t)(kt & 1) * 32768;

        if (kt < 31) {
            uint32_t bufn = sb + (uint32_t)((kt + 1) & 1) * 32768;
            int m0n = (kt0 + kt + 1) * 64;
            #pragma unroll
            for (int u = 0; u < 2; u++) {
                int i = tid + u * 256;
                int row = i >> 3, ch = i & 7;
                uint32_t dst = bufn + row * 128 + (((ch ^ (row & 7))) << 4);
                long go = (long)row * HW + m0n + ch * 8;
                cpa16(dst,          Kh + go);
                cpa16(dst + 8192,   Kl + go);
                cpa16(dst + 16384,  Vh + go);
                cpa16(dst + 24576,  Vl + go);
            }
            CPA_COMMIT();
            CPA_WAIT1();
        } else {
            CPA_WAIT0();
        }
        __syncthreads();

        float sa[8][4];
        #pragma unroll
        for (int nb = 0; nb < 8; nb++) {
            sa[nb][0] = 0.f; sa[nb][1] = 0.f; sa[nb][2] = 0.f; sa[nb][3] = 0.f;
        }
        #pragma unroll
        for (int kc = 0; kc < 4; kc++) {
            #pragma unroll
            for (int jb = 0; jb < 4; jb++) {
                uint32_t bh[4], bl[4];
                uint32_t koff = (uint32_t)((kc * 16 + rl) * 128 +
                                           (((jb * 2 + hi_half) ^ r7) << 4));
                ldsm4t(bh, bufc + koff);
                ldsm4t(bl, bufc + 8192 + koff);
                mma_bf16(sa[2 * jb],     qh[kc], bh[0], bh[1]);
                mma_bf16(sa[2 * jb],     qh[kc], bl[0], bl[1]);
                mma_bf16(sa[2 * jb],     ql[kc], bh[0], bh[1]);
                mma_bf16(sa[2 * jb + 1], qh[kc], bh[2], bh[3]);
                mma_bf16(sa[2 * jb + 1], qh[kc], bl[2], bl[3]);
                mma_bf16(sa[2 * jb + 1], ql[kc], bh[2], bh[3]);
            }
        }

        float tm0 = -1e30f, tm1 = -1e30f;
        #pragma unroll
        for (int nb = 0; nb < 8; nb++) {
            tm0 = fmaxf(tm0, fmaxf(sa[nb][0], sa[nb][1]));
            tm1 = fmaxf(tm1, fmaxf(sa[nb][2], sa[nb][3]));
        }
        tm0 = fmaxf(tm0, __shfl_xor_sync(0xffffffffu, tm0, 1));
        tm0 = fmaxf(tm0, __shfl_xor_sync(0xffffffffu, tm0, 2));
        tm1 = fmaxf(tm1, __shfl_xor_sync(0xffffffffu, tm1, 1));
        tm1 = fmaxf(tm1, __shfl_xor_sync(0xffffffffu, tm1, 2));
        float mn0 = fmaxf(mrow0, tm0), mn1 = fmaxf(mrow1, tm1);
        float corr0 = __expf(mrow0 - mn0), corr1 = __expf(mrow1 - mn1);
        mrow0 = mn0; mrow1 = mn1;

        float ps0 = 0.f, ps1 = 0.f;
        #pragma unroll
        for (int nb = 0; nb < 8; nb++) {
            sa[nb][0] = __expf(sa[nb][0] - mn0);
            sa[nb][1] = __expf(sa[nb][1] - mn0);
            sa[nb][2] = __expf(sa[nb][2] - mn1);
            sa[nb][3] = __expf(sa[nb][3] - mn1);
            ps0 += sa[nb][0] + sa[nb][1];
            ps1 += sa[nb][2] + sa[nb][3];
        }
        ps0 += __shfl_xor_sync(0xffffffffu, ps0, 1);
        ps0 += __shfl_xor_sync(0xffffffffu, ps0, 2);
        ps1 += __shfl_xor_sync(0xffffffffu, ps1, 1);
        ps1 += __shfl_xor_sync(0xffffffffu, ps1, 2);
        lrow0 = lrow0 * corr0 + ps0;
        lrow1 = lrow1 * corr1 + ps1;

        #pragma unroll
        for (int cb = 0; cb < 8; cb++) {
            oacc[cb][0] *= corr0; oacc[cb][1] *= corr0;
            oacc[cb][2] *= corr1; oacc[cb][3] *= corr1;
        }

        uint32_t ph[4][4], pl[4][4];
        #pragma unroll
        for (int kc = 0; kc < 4; kc++) {
            split2(sa[2 * kc][0],     sa[2 * kc][1],     ph[kc][0], pl[kc][0]);
            split2(sa[2 * kc][2],     sa[2 * kc][3],     ph[kc][1], pl[kc][1]);
            split2(sa[2 * kc + 1][0], sa[2 * kc + 1][1], ph[kc][2], pl[kc][2]);
            split2(sa[2 * kc + 1][2], sa[2 * kc + 1][3], ph[kc][3], pl[kc][3]);
        }

        #pragma unroll
        for (int kc = 0; kc < 4; kc++) {
            #pragma unroll
            for (int cp = 0; cp < 4; cp++) {
                uint32_t bh[4], bl[4];
                uint32_t voff = (uint32_t)((cp * 16 + vrow) * 128 +
                                           (((kc * 2 + vch) ^ v7) << 4));
                ldsm4(bh, bufc + 16384 + voff);
                ldsm4(bl, bufc + 24576 + voff);
                mma_bf16(oacc[2 * cp],     ph[kc], bh[0], bh[1]);
                mma_bf16(oacc[2 * cp],     ph[kc], bl[0], bl[1]);
                mma_bf16(oacc[2 * cp],     pl[kc], bh[0], bh[1]);
                mma_bf16(oacc[2 * cp + 1], ph[kc], bh[2], bh[3]);
                mma_bf16(oacc[2 * cp + 1], ph[kc], bl[2], bl[3]);
                mma_bf16(oacc[2 * cp + 1], pl[kc], bh[2], bh[3]);
            }
        }
        __syncthreads();
    }

    long pbase = ((((long)kind * BATCH + b) * NSP + sp) * CH) * HW;
    int i0 = n0 + 16 * wid + g;
    #pragma unroll
    for (int cb = 0; cb < 8; cb++) {
        int c = 8 * cb + 2 * tg;
        g_pO[pbase + (long)c * HW + i0]           = oacc[cb][0];
        g_pO[pbase + (long)(c + 1) * HW + i0]     = oacc[cb][1];
        g_pO[pbase + (long)c * HW + i0 + 8]       = oacc[cb][2];
        g_pO[pbase + (long)(c + 1) * HW + i0 + 8] = oacc[cb][3];
    }
    if (tg == 0) {
        long mb = (((long)kind * 2 + b) * NSP + sp) * HW;
        g_pm[mb + i0] = mrow0;     g_pl[mb + i0] = lrow0;
        g_pm[mb + i0 + 8] = mrow1; g_pl[mb + i0 + 8] = lrow1;
    }
}

// ---------------- 4b. merge splits + combine + shortcut 1x1, all fused ----------------
// grid (64, BATCH), block 256. Block: 64 pixels, all 64 channels.
__global__ void __launch_bounds__(256) kmergec(const float* __restrict__ gamma,
                                               const float* __restrict__ alpha,
                                               const float* __restrict__ sc_w,
                                               const float* __restrict__ sc_b) {
    __shared__ float so[64 * 64];     // outb tile [c][px]
    __shared__ float swt[64 * 64];    // sc weights transposed [c][oc]

    int b = blockIdx.y;
    int p0 = blockIdx.x * 64;
    int tid = threadIdx.x;

    for (int i = tid; i < 4096; i += 256) {
        int c = i >> 6, o = i & 63;
        swt[c * 64 + o] = sc_w[o * 64 + c];
    }

    float ga = gamma[0], al = alpha[0];
    for (int idx = tid; idx < 4096; idx += 256) {
        int c = idx >> 6, i = idx & 63;
        int ii = p0 + i;
        float o01[2];
        #pragma unroll
        for (int kind = 0; kind < 2; kind++) {
            long mb = (((long)kind * 2 + b) * NSP) * HW;
            float m0 = g_pm[mb + ii], m1 = g_pm[mb + HW + ii];
            float l0 = g_pl[mb + ii], l1 = g_pl[mb + HW + ii];
            float m = fmaxf(m0, m1);
            float w0 = __expf(m0 - m), w1 = __expf(m1 - m);
            float inv = 1.f / (w0 * l0 + w1 * l1);
            long ob = ((((long)kind * BATCH + b) * NSP) * CH + c) * HW + ii;
            o01[kind] = (w0 * g_pO[ob] + w1 * g_pO[ob + (long)CH * HW]) * inv;
        }
        float ob = ga * o01[0] + al * o01[1];
        so[c * 64 + idx % 64] = ob;
        int di = (b * CH + c) * HW + ii;
        g_outb[di] = ob;
        g_gout[di] = o01[1];
    }
    __syncthreads();

    // shortcut 1x1: px = tid & 63, group of 16 oc = tid >> 6
    int px = tid & 63, grp = tid >> 6;
    float acc[16];
    #pragma unroll
    for (int o = 0; o < 16; o++) acc[o] = sc_b[grp * 16 + o];
    for (int c = 0; c < 64; c++) {
        float iv = so[c * 64 + px];
        #pragma unroll
        for (int o = 0; o < 16; o++)
            acc[o] += swt[c * 64 + grp * 16 + o] * iv;
    }
    #pragma unroll
    for (int o = 0; o < 16; o++)
        g_sc[(b * CH + grp * 16 + o) * HW + p0 + px] = acc[o];
}

// ---------------- 6. plain conv3x3: 4 oc, 2 px/thread, optional fused final ----------------
__global__ void __launch_bounds__(256) kconv3(const float* __restrict__ w,
                                              const float* __restrict__ bias,
                                              int in_id, int out_id, int leaky_in,
                                              int finalize, float* __restrict__ dout) {
    const float* inb = pick_in(in_id);
    int b = blockIdx.z, ocg = blockIdx.y;

    __shared__ float ws[4 * 576];
    for (int i = threadIdx.x; i < 4 * 576; i += 256) {
        int o = i / 576, r = i % 576;
        ws[o * 576 + r] = w[(ocg * 4 + o) * 576 + r];
    }
    __syncthreads();

    int p = blockIdx.x * 512 + threadIdx.x * 2;
    int row = p >> 6, col0 = p & 63;
    float acc[4][2];
    #pragma unroll
    for (int o = 0; o < 4; o++) {
        float bv = bias[ocg * 4 + o];
        acc[o][0] = bv; acc[o][1] = bv;
    }
    const float* in = inb + b * CH * HW;

    for (int ic = 0; ic < 64; ic++) {
        const float* ch = in + ic * HW;
        #pragma unroll
        for (int kh = 0; kh < 3; kh++) {
            int hh = row + kh - 1;
            if ((unsigned)hh >= 64u) continue;
            float v[4];
            #pragma unroll
            for (int u = 0; u < 4; u++) {
                int cc = col0 - 1 + u;
                float val = ((unsigned)cc < 64u) ? ch[hh * 64 + cc] : 0.f;
                if (leaky_in) val = val > 0.f ? val : 0.1f * val;
                v[u] = val;
            }
            #pragma unroll
            for (int o = 0; o < 4; o++) {
                const float* wr = &ws[o * 576 + ic * 9 + kh * 3];
                #pragma unroll
                for (int kw = 0; kw < 3; kw++) {
                    float wv = wr[kw];
                    acc[o][0] += wv * v[kw + 0];
                    acc[o][1] += wv * v[kw + 1];
                }
            }
        }
    }
    if (finalize) {
        #pragma unroll
        for (int o = 0; o < 4; o++) {
            int base = (b * CH + ocg * 4 + o) * HW + p;
            float2 scv = *(const float2*)(g_sc + base);
            float2 gov = *(const float2*)(g_gout + base);
            *(float2*)(dout + base) = make_float2(acc[o][0] + scv.x * gov.x,
                                                  acc[o][1] + scv.y * gov.y);
        }
    } else {
        float* outb = pick_out(out_id);
        #pragma unroll
        for (int o = 0; o < 4; o++) {
            float* op = outb + (b * CH + ocg * 4 + o) * HW + p;
            *(float2*)op = make_float2(acc[o][0], acc[o][1]);
        }
    }
}

extern "C" void kernel_launch(void* const* d_in, const int* in_sizes, int n_in,
                              void* d_out, int out_size) {
    const float* x       = (const float*)d_in[0];
    const float* guide   = (const float*)d_in[1];
    const float* lin_w   = (const float*)d_in[2];
    const float* lin_b   = (const float*)d_in[3];
    const float* coord_w = (const float*)d_in[4];
    const float* xq_w = (const float*)d_in[5];
    const float* xq_b = (const float*)d_in[6];
    const float* xk_w = (const float*)d_in[7];
    const float* xk_b = (const float*)d_in[8];
    const float* xv_w = (const float*)d_in[9];
    const float* xv_b = (const float*)d_in[10];
    const float* gq_w = (const float*)d_in[11];
    const float* gq_b = (const float*)d_in[12];
    const float* gk_w = (const float*)d_in[13];
    const float* gk_b = (const float*)d_in[14];
    const float* gamma = (const float*)d_in[15];
    const float* alpha = (const float*)d_in[16];
    const float* c1_w = (const float*)d_in[17];
    const float* c1_b = (const float*)d_in[18];
    const float* c2_w = (const float*)d_in[19];
    const float* c2_b = (const float*)d_in[20];
    const float* sc_w = (const float*)d_in[21];
    const float* sc_b = (const float*)d_in[22];
    float* out = (float*)d_out;

    cudaFuncSetAttribute(kattn, cudaFuncAttributeMaxDynamicSharedMemorySize, 65536);

    kstats<<<256, 256>>>(x, guide, lin_w, lin_b);
    kgated<<<dim3(8, 16, 4), 256>>>(x, guide, coord_w);

    kproj<<<dim3(32, 8, 4), 128>>>(xq_w, xq_b, xk_w, xk_b, xv_w, xv_b,
                                   gq_w, gq_b, gk_w, gk_b);

    kattn<<<dim3(32 * NSP, BATCH, 2), 256, 65536>>>();
    kmergec<<<dim3(64, BATCH), 256>>>(gamma, alpha, sc_w, sc_b);

    kconv3<<<dim3(8, 16, BATCH), 256>>>(c1_w, c1_b, BUF_OUT, BUF_OT1, 1, 0, nullptr);
    kconv3<<<dim3(8, 16, BATCH), 256>>>(c2_w, c2_b, BUF_T1, 0, 1, 1, out);
}

// round 15
// speedup vs baseline: 1.0120x; 1.0120x over previous
#include <cuda_runtime.h>
#include <cuda_bf16.h>
#include <cstdint>

#define BATCH 2
#define CH 64
#define HW 4096   // 64*64
#define NSP 2     // KV splits
#define LOG2E 1.4426950408889634f

typedef unsigned long long u64;

__device__ __forceinline__ u64 pk2(float lo, float hi) {
    u64 r; asm("mov.b64 %0,{%1,%2};" : "=l"(r) : "f"(lo), "f"(hi)); return r;
}
__device__ __forceinline__ void upk2(u64 v, float& lo, float& hi) {
    asm("mov.b64 {%0,%1},%2;" : "=f"(lo), "=f"(hi) : "l"(v));
}
__device__ __forceinline__ u64 ffma2(u64 a, u64 b, u64 c) {
    u64 d; asm("fma.rn.f32x2 %0,%1,%2,%3;" : "=l"(d) : "l"(a), "l"(b), "l"(c)); return d;
}

// ---------------- scratch ----------------
__device__ float g_scale[4 * CH];
__device__ float g_xg[BATCH * CH * HW];
__device__ float g_gg[BATCH * CH * HW];
__device__ float g_xq[BATCH * CH * HW];
__device__ float g_gq[BATCH * CH * HW];
__device__ float g_gout[BATCH * CH * HW];
__device__ float g_outb[BATCH * CH * HW];
__device__ float g_t1[BATCH * CH * HW];
__device__ float g_sc[BATCH * CH * HW];
__device__ __nv_bfloat16 g_bkh[2 * BATCH * CH * HW];
__device__ __nv_bfloat16 g_bkl[2 * BATCH * CH * HW];
__device__ __nv_bfloat16 g_bvh[BATCH * CH * HW];
__device__ __nv_bfloat16 g_bvl[BATCH * CH * HW];
// split-KV partials
__device__ float g_pO[2 * BATCH * NSP * CH * HW];
__device__ float g_pm[2 * BATCH * NSP * HW];
__device__ float g_pl[2 * BATCH * NSP * HW];

#define BUF_XG 0
#define BUF_GG 1
#define BUF_OUT 2
#define BUF_T1 3

#define BUF_SC 5
#define BUF_OT1 6

__device__ __forceinline__ float* pick_in(int w) {
    switch (w) {
        case BUF_XG: return g_xg;
        case BUF_GG: return g_gg;
        case BUF_OUT: return g_outb;
        default:     return g_t1;
    }
}
__device__ __forceinline__ float* pick_out(int w) {
    switch (w) {
        case BUF_SC: return g_sc;
        default:     return g_t1;
    }
}

// ================= helpers =================
__device__ __forceinline__ uint32_t su32(const void* p) {
    uint32_t a;
    asm("{ .reg .u64 t; cvta.to.shared.u64 t, %1; cvt.u32.u64 %0, t; }" : "=r"(a) : "l"(p));
    return a;
}
__device__ __forceinline__ void mma_bf16(float* d, const uint32_t* a, uint32_t b0, uint32_t b1) {
    asm volatile(
        "mma.sync.aligned.m16n8k16.row.col.f32.bf16.bf16.f32 "
        "{%0,%1,%2,%3}, {%4,%5,%6,%7}, {%8,%9}, {%0,%1,%2,%3};"
        : "+f"(d[0]), "+f"(d[1]), "+f"(d[2]), "+f"(d[3])
        : "r"(a[0]), "r"(a[1]), "r"(a[2]), "r"(a[3]), "r"(b0), "r"(b1));
}
__device__ __forceinline__ void ldsm4(uint32_t* r, uint32_t addr) {
    asm volatile("ldmatrix.sync.aligned.m8n8.x4.shared.b16 {%0,%1,%2,%3}, [%4];"
                 : "=r"(r[0]), "=r"(r[1]), "=r"(r[2]), "=r"(r[3]) : "r"(addr));
}
__device__ __forceinline__ void ldsm4t(uint32_t* r, uint32_t addr) {
    asm volatile("ldmatrix.sync.aligned.m8n8.x4.trans.shared.b16 {%0,%1,%2,%3}, [%4];"
                 : "=r"(r[0]), "=r"(r[1]), "=r"(r[2]), "=r"(r[3]) : "r"(addr));
}
__device__ __forceinline__ uint32_t cvt_bf2(float lo, float hi) {
    uint32_t r;
    asm("cvt.rn.bf16x2.f32 %0, %1, %2;" : "=r"(r) : "f"(hi), "f"(lo));
    return r;
}
__device__ __forceinline__ void split2(float a, float b, uint32_t& hw, uint32_t& lw) {
    uint32_t h = cvt_bf2(a, b);
    float ra = a - __uint_as_float(h << 16);
    float rb = b - __uint_as_float(h & 0xFFFF0000u);
    hw = h;
    lw = cvt_bf2(ra, rb);
}
__device__ __forceinline__ void wrb(__nv_bfloat16* H, __nv_bfloat16* L, int idx, float v) {
    __nv_bfloat16 h = __float2bfloat16_rn(v);
    H[idx] = h;
    L[idx] = __float2bfloat16_rn(v - __bfloat162float(h));
}
__device__ __forceinline__ void cpa16(uint32_t dst, const void* src) {
    asm volatile("cp.async.cg.shared.global [%0], [%1], 16;" :: "r"(dst), "l"(src) : "memory");
}
#define CPA_COMMIT() asm volatile("cp.async.commit_group;" ::: "memory")
#define CPA_WAIT1()  asm volatile("cp.async.wait_group 1;" ::: "memory")
#define CPA_WAIT0()  asm volatile("cp.async.wait_group 0;" ::: "memory")

// ---------------- 1. channel attention scalars ----------------
__global__ void kstats(const float* __restrict__ x, const float* __restrict__ g,
                       const float* __restrict__ lw, const float* __restrict__ lb) {
    int idx = blockIdx.x;
    int t = idx >> 7, b = (idx >> 6) & 1, c = idx & 63;
    const float* in = (t ? g : x) + (b * CH + c) * HW;
    float s = 0.f;
    for (int i = threadIdx.x; i < HW; i += 256) s += in[i];
    __shared__ float red[8];
    #pragma unroll
    for (int o = 16; o > 0; o >>= 1) s += __shfl_xor_sync(0xffffffffu, s, o);
    if ((threadIdx.x & 31) == 0) red[threadIdx.x >> 5] = s;
    __syncthreads();
    if (threadIdx.x == 0) {
        float tot = 0.f;
        #pragma unroll
        for (int i = 0; i < 8; i++) tot += red[i];
        float p = tot * (1.0f / (float)HW);
        float W = lw[0], B = lb[0];
        float h = p * W + B;
        h = h > 0.f ? h : 0.1f * h;
        float z = h * W + B;
        g_scale[idx] = 1.f / (1.f + expf(-z));
    }
}

// ---------------- 2. gated coord conv: 4 oc, 2 px/thread, 512 CTAs ----------------
__global__ void __launch_bounds__(256) kgated(const float* __restrict__ xin,
                                              const float* __restrict__ gin,
                                              const float* __restrict__ cw) {
    int z = blockIdx.z;
    int t = z >> 1, b = z & 1;
    const float* in = (t ? gin : xin) + b * CH * HW;
    float* out = (t ? g_gg : g_xg) + b * CH * HW;
    int ocg = blockIdx.y;

    __shared__ float ws[4 * 66 * 9];
    for (int i = threadIdx.x; i < 4 * 594; i += 256) {
        int o = i / 594, r = i % 594;
        ws[o * 594 + r] = cw[(ocg * 4 + o) * 594 + r];
    }
    __syncthreads();

    int p = blockIdx.x * 512 + threadIdx.x * 2;
    int row = p >> 6, col0 = p & 63;
    float acc[4][2];
    #pragma unroll
    for (int o = 0; o < 4; o++) { acc[o][0] = 0.f; acc[o][1] = 0.f; }

    for (int ic = 0; ic < 64; ic++) {
        const float* ch = in + ic * HW;
        #pragma unroll
        for (int kh = 0; kh < 3; kh++) {
            int hh = row + kh - 1;
            if ((unsigned)hh >= 64u) continue;
            float v[4];
            #pragma unroll
            for (int u = 0; u < 4; u++) {
                int cc = col0 - 1 + u;
                v[u] = ((unsigned)cc < 64u) ? ch[hh * 64 + cc] : 0.f;
            }
            #pragma unroll
            for (int o = 0; o < 4; o++) {
                const float* wr = &ws[o * 594 + ic * 9 + kh * 3];
                #pragma unroll
                for (int kw = 0; kw < 3; kw++) {
                    float wv = wr[kw];
                    acc[o][0] += wv * v[kw + 0];
                    acc[o][1] += wv * v[kw + 1];
                }
            }
        }
    }
    #pragma unroll
    for (int ic = 64; ic < 66; ic++) {
        #pragma unroll
        for (int kh = 0; kh < 3; kh++) {
            int hh = row + kh - 1;
            if ((unsigned)hh >= 64u) continue;
            float yyv = (float)hh * (2.f / 63.f) - 1.f;
            float v[4];
            #pragma unroll
            for (int u = 0; u < 4; u++) {
                int cc = col0 - 1 + u;
                float val = 0.f;
                if ((unsigned)cc < 64u)
                    val = (ic == 64) ? ((float)cc * (2.f / 63.f) - 1.f) : yyv;
                v[u] = val;
            }
            #pragma unroll
            for (int o = 0; o < 4; o++) {
                const float* wr = &ws[o * 594 + ic * 9 + kh * 3];
                #pragma unroll
                for (int kw = 0; kw < 3; kw++) {
                    float wv = wr[kw];
                    acc[o][0] += wv * v[kw + 0];
                    acc[o][1] += wv * v[kw + 1];
                }
            }
        }
    }

    #pragma unroll
    for (int o = 0; o < 4; o++) {
        int oc = ocg * 4 + o;
        float s = g_scale[z * CH + oc];
        *(float2*)(out + oc * HW + p) = make_float2(s * acc[o][0], s * acc[o][1]);
    }
}

// ---------------- 3. fused QKV projections; K/V written as bf16 hi/lo ----------------
__global__ void __launch_bounds__(128) kproj(
    const float* __restrict__ xq_w, const float* __restrict__ xq_b,
    const float* __restrict__ xk_w, const float* __restrict__ xk_b,
    const float* __restrict__ xv_w, const float* __restrict__ xv_b,
    const float* __restrict__ gq_w, const float* __restrict__ gq_b,
    const float* __restrict__ gk_w, const float* __restrict__ gk_b) {
    __shared__ float si[64 * 128];
    __shared__ float swt[3 * 512];
    __shared__ float sb2[3 * 8];

    int z = blockIdx.z;
    int side = z >> 1, b = z & 1;
    int og = blockIdx.y;
    int n0 = blockIdx.x * 128;
    int tid = threadIdx.x;

    const float* in = (side ? g_gg : g_xg) + b * CH * HW;
    const float* ws[3];
    const float* bs[3];
    int nset;
    if (side == 0) {
        ws[0] = xq_w; ws[1] = xk_w; ws[2] = xv_w;
        bs[0] = xq_b; bs[1] = xk_b; bs[2] = xv_b;
        nset = 3;
    } else {
        ws[0] = gq_w; ws[1] = gk_w; ws[2] = gk_w;
        bs[0] = gq_b; bs[1] = gk_b; bs[2] = gk_b;
        nset = 2;
    }

    for (int i = tid; i < 2048; i += 128) {
        int c = i >> 5, p4 = (i & 31) * 4;
        *(float4*)(si + c * 128 + p4) = *(const float4*)(in + c * HW + n0 + p4);
    }
    for (int s = 0; s < nset; s++) {
        for (int i = tid; i < 512; i += 128) {
            int c = i >> 3, o = i & 7;
            swt[s * 512 + c * 8 + o] = ws[s][(og * 8 + o) * 64 + c];
        }
        if (tid < 8) sb2[s * 8 + tid] = bs[s][og * 8 + tid];
    }
    __syncthreads();

    u64 acc[3][4];
    #pragma unroll
    for (int s = 0; s < 3; s++)
        #pragma unroll
        for (int k = 0; k < 4; k++)
            acc[s][k] = pk2(sb2[s * 8 + 2 * k], sb2[s * 8 + 2 * k + 1]);

    if (side == 0) {
        for (int c = 0; c < 64; c++) {
            float iv = si[c * 128 + tid];
            u64 ivp = pk2(iv, iv);
            #pragma unroll
            for (int s = 0; s < 3; s++) {
                ulonglong2 wa = *(const ulonglong2*)(swt + s * 512 + c * 8);
                ulonglong2 wb = *(const ulonglong2*)(swt + s * 512 + c * 8 + 4);
                acc[s][0] = ffma2(ivp, wa.x, acc[s][0]);
                acc[s][1] = ffma2(ivp, wa.y, acc[s][1]);
                acc[s][2] = ffma2(ivp, wb.x, acc[s][2]);
                acc[s][3] = ffma2(ivp, wb.y, acc[s][3]);
            }
        }
    } else {
        for (int c = 0; c < 64; c++) {
            float iv = si[c * 128 + tid];
            u64 ivp = pk2(iv, iv);
            #pragma unroll
            for (int s = 0; s < 2; s++) {
                ulonglong2 wa = *(const ulonglong2*)(swt + s * 512 + c * 8);
                ulonglong2 wb = *(const ulonglong2*)(swt + s * 512 + c * 8 + 4);
                acc[s][0] = ffma2(ivp, wa.x, acc[s][0]);
                acc[s][1] = ffma2(ivp, wa.y, acc[s][1]);
                acc[s][2] = ffma2(ivp, wb.x, acc[s][2]);
                acc[s][3] = ffma2(ivp, wb.y, acc[s][3]);
            }
        }
    }

    float* qdst = side ? g_gq : g_xq;
    __nv_bfloat16* KhD = g_bkh + (long)side * BATCH * CH * HW;
    __nv_bfloat16* KlD = g_bkl + (long)side * BATCH * CH * HW;
    #pragma unroll
    for (int k = 0; k < 4; k++) {
        int i0 = (b * CH + og * 8 + 2 * k) * HW + n0 + tid;
        float lo, hi;
        upk2(acc[0][k], lo, hi);
        qdst[i0] = lo; qdst[i0 + HW] = hi;
        upk2(acc[1][k], lo, hi);
        wrb(KhD, KlD, i0, lo); wrb(KhD, KlD, i0 + HW, hi);
        if (side == 0) {
            upk2(acc[2][k], lo, hi);
            wrb(g_bvh, g_bvl, i0, lo); wrb(g_bvh, g_bvl, i0 + HW, hi);
        }
    }
}

// ---------------- 4. flash attention: split-KV, 256 threads, double-buffered, 1 wave ----------------
// Q scaled by log2(e) at staging -> softmax in base-2 domain (exp2f, partial m in log2 units).
__global__ void __launch_bounds__(256, 2) kattn() {
    extern __shared__ __align__(16) uint8_t dyn[];

    const int tid = threadIdx.x;
    const int lane = tid & 31, wid = tid >> 5;
    const int tg = lane & 3, g = lane >> 2;
    const int b = blockIdx.y, kind = blockIdx.z;
    const int nt = blockIdx.x >> 1, sp = blockIdx.x & 1;
    const int n0 = nt * 128;
    const int kt0 = sp * 32;
    const float* Qp = (kind ? g_gq : g_xq) + b * CH * HW;
    const __nv_bfloat16* Kh = g_bkh + ((long)kind * BATCH + b) * CH * HW;
    const __nv_bfloat16* Kl = g_bkl + ((long)kind * BATCH + b) * CH * HW;
    const __nv_bfloat16* Vh = g_bvh + (long)b * CH * HW;
    const __nv_bfloat16* Vl = g_bvl + (long)b * CH * HW;

    const uint32_t sb = su32(dyn);

    for (int idx = tid; idx < 8192; idx += 256) {
        int i = idx & 127, c = idx >> 7;
        float a = Qp[c * HW + n0 + i] * LOG2E;
        __nv_bfloat16 h = __float2bfloat16_rn(a);
        uint32_t off = (uint32_t)(i * 128 + ((((c >> 3) ^ (i & 7))) << 4) + (c & 7) * 2);
        *(__nv_bfloat16*)(dyn + off) = h;
        *(__nv_bfloat16*)(dyn + 16384 + off) = __float2bfloat16_rn(a - __bfloat162float(h));
    }
    __syncthreads();

    const int rl = lane & 15, hi_half = lane >> 4, r7 = rl & 7;
    uint32_t qh[4][4], ql[4][4];
    #pragma unroll
    for (int kc = 0; kc < 4; kc++) {
        uint32_t off = (uint32_t)((16 * wid + rl) * 128 + (((kc * 2 + hi_half) ^ r7) << 4));
        ldsm4(qh[kc], sb + off);
        ldsm4(ql[kc], sb + 16384 + off);
    }
    __syncthreads();

    float oacc[8][4];
    #pragma unroll
    for (int cb = 0; cb < 8; cb++) {
        oacc[cb][0] = 0.f; oacc[cb][1] = 0.f; oacc[cb][2] = 0.f; oacc[cb][3] = 0.f;
    }
    float mrow0 = -1e30f, mrow1 = -1e30f, lrow0 = 0.f, lrow1 = 0.f;

    const int vrow = ((lane >> 4) << 3) + (lane & 7);
    const int vch = (lane >> 3) & 1;
    const int v7 = lane & 7;

    {
        int m0 = kt0 * 64;
        #pragma unroll
        for (int u = 0; u < 2; u++) {
            int i = tid + u * 256;
            int row = i >> 3, ch = i & 7;
            uint32_t dst = sb + row * 128 + (((ch ^ (row & 7))) << 4);
            long go = (long)row * HW + m0 + ch * 8;
            cpa16(dst,          Kh + go);
            cpa16(dst + 8192,   Kl + go);
            cpa16(dst + 16384,  Vh + go);
            cpa16(dst + 24576,  Vl + go);
        }
        CPA_COMMIT();
    }

    for (int kt = 0; kt < 32; kt++) {
        const uint32_t bufc = sb + (uint32_t)(kt & 1) * 32768;

        if (kt < 31) {
            uint32_t bufn = sb + (uint32_t)((kt + 1) & 1) * 32768;
            int m0n = (kt0 + kt + 1) * 64;
            #pragma unroll
            for (int u = 0; u < 2; u++) {
                int i = tid + u * 256;
                int row = i >> 3, ch = i & 7;
                uint32_t dst = bufn + row * 128 + (((ch ^ (row & 7))) << 4);
                long go = (long)row * HW + m0n + ch * 8;
                cpa16(dst,          Kh + go);
                cpa16(dst + 8192,   Kl + go);
                cpa16(dst + 16384,  Vh + go);
                cpa16(dst + 24576,  Vl + go);
            }
            CPA_COMMIT();
            CPA_WAIT1();
        } else {
            CPA_WAIT0();
        }
        __syncthreads();

        float sa[8][4];
        #pragma unroll
        for (int nb = 0; nb < 8; nb++) {
            sa[nb][0] = 0.f; sa[nb][1] = 0.f; sa[nb][2] = 0.f; sa[nb][3] = 0.f;
        }
        #pragma unroll
        for (int kc = 0; kc < 4; kc++) {
            #pragma unroll
            for (int jb = 0; jb < 4; jb++) {
                uint32_t bh[4], bl[4];
                uint32_t koff = (uint32_t)((kc * 16 + rl) * 128 +
                                           (((jb * 2 + hi_half) ^ r7) << 4));
                ldsm4t(bh, bufc + koff);
                ldsm4t(bl, bufc + 8192 + koff);
                mma_bf16(sa[2 * jb],     qh[kc], bh[0], bh[1]);
                mma_bf16(sa[2 * jb],     qh[kc], bl[0], bl[1]);
                mma_bf16(sa[2 * jb],     ql[kc], bh[0], bh[1]);
                mma_bf16(sa[2 * jb + 1], qh[kc], bh[2], bh[3]);
                mma_bf16(sa[2 * jb + 1], qh[kc], bl[2], bl[3]);
                mma_bf16(sa[2 * jb + 1], ql[kc], bh[2], bh[3]);
            }
        }

        float tm0 = -1e30f, tm1 = -1e30f;
        #pragma unroll
        for (int nb = 0; nb < 8; nb++) {
            tm0 = fmaxf(tm0, fmaxf(sa[nb][0], sa[nb][1]));
            tm1 = fmaxf(tm1, fmaxf(sa[nb][2], sa[nb][3]));
        }
        tm0 = fmaxf(tm0, __shfl_xor_sync(0xffffffffu, tm0, 1));
        tm0 = fmaxf(tm0, __shfl_xor_sync(0xffffffffu, tm0, 2));
        tm1 = fmaxf(tm1, __shfl_xor_sync(0xffffffffu, tm1, 1));
        tm1 = fmaxf(tm1, __shfl_xor_sync(0xffffffffu, tm1, 2));
        float mn0 = fmaxf(mrow0, tm0), mn1 = fmaxf(mrow1, tm1);
        float corr0 = exp2f(mrow0 - mn0), corr1 = exp2f(mrow1 - mn1);
        mrow0 = mn0; mrow1 = mn1;

        float ps0 = 0.f, ps1 = 0.f;
        #pragma unroll
        for (int nb = 0; nb < 8; nb++) {
            sa[nb][0] = exp2f(sa[nb][0] - mn0);
            sa[nb][1] = exp2f(sa[nb][1] - mn0);
            sa[nb][2] = exp2f(sa[nb][2] - mn1);
            sa[nb][3] = exp2f(sa[nb][3] - mn1);
            ps0 += sa[nb][0] + sa[nb][1];
            ps1 += sa[nb][2] + sa[nb][3];
        }
        ps0 += __shfl_xor_sync(0xffffffffu, ps0, 1);
        ps0 += __shfl_xor_sync(0xffffffffu, ps0, 2);
        ps1 += __shfl_xor_sync(0xffffffffu, ps1, 1);
        ps1 += __shfl_xor_sync(0xffffffffu, ps1, 2);
        lrow0 = lrow0 * corr0 + ps0;
        lrow1 = lrow1 * corr1 + ps1;

        #pragma unroll
        for (int cb = 0; cb < 8; cb++) {
            oacc[cb][0] *= corr0; oacc[cb][1] *= corr0;
            oacc[cb][2] *= corr1; oacc[cb][3] *= corr1;
        }

        uint32_t ph[4][4], pl[4][4];
        #pragma unroll
        for (int kc = 0; kc < 4; kc++) {
            split2(sa[2 * kc][0],     sa[2 * kc][1],     ph[kc][0], pl[kc][0]);
            split2(sa[2 * kc][2],     sa[2 * kc][3],     ph[kc][1], pl[kc][1]);
            split2(sa[2 * kc + 1][0], sa[2 * kc + 1][1], ph[kc][2], pl[kc][2]);
            split2(sa[2 * kc + 1][2], sa[2 * kc + 1][3], ph[kc][3], pl[kc][3]);
        }

        #pragma unroll
        for (int kc = 0; kc < 4; kc++) {
            #pragma unroll
            for (int cp = 0; cp < 4; cp++) {
                uint32_t bh[4], bl[4];
                uint32_t voff = (uint32_t)((cp * 16 + vrow) * 128 +
                                           (((kc * 2 + vch) ^ v7) << 4));
                ldsm4(bh, bufc + 16384 + voff);
                ldsm4(bl, bufc + 24576 + voff);
                mma_bf16(oacc[2 * cp],     ph[kc], bh[0], bh[1]);
                mma_bf16(oacc[2 * cp],     ph[kc], bl[0], bl[1]);
                mma_bf16(oacc[2 * cp],     pl[kc], bh[0], bh[1]);
                mma_bf16(oacc[2 * cp + 1], ph[kc], bh[2], bh[3]);
                mma_bf16(oacc[2 * cp + 1], ph[kc], bl[2], bl[3]);
                mma_bf16(oacc[2 * cp + 1], pl[kc], bh[2], bh[3]);
            }
        }
        __syncthreads();
    }

    long pbase = ((((long)kind * BATCH + b) * NSP + sp) * CH) * HW;
    int i0 = n0 + 16 * wid + g;
    #pragma unroll
    for (int cb = 0; cb < 8; cb++) {
        int c = 8 * cb + 2 * tg;
        g_pO[pbase + (long)c * HW + i0]           = oacc[cb][0];
        g_pO[pbase + (long)(c + 1) * HW + i0]     = oacc[cb][1];
        g_pO[pbase + (long)c * HW + i0 + 8]       = oacc[cb][2];
        g_pO[pbase + (long)(c + 1) * HW + i0 + 8] = oacc[cb][3];
    }
    if (tg == 0) {
        long mb = (((long)kind * 2 + b) * NSP + sp) * HW;
        g_pm[mb + i0] = mrow0;     g_pl[mb + i0] = lrow0;
        g_pm[mb + i0 + 8] = mrow1; g_pl[mb + i0 + 8] = lrow1;
    }
}

// ---------------- 4b. merge 2 splits + combine (gamma/alpha) fused ----------------
// m partials are in log2 domain -> exp2f weights.
__global__ void kmergec(const float* __restrict__ gamma, const float* __restrict__ alpha) {
    int t = blockIdx.x * 256 + threadIdx.x;
    int i = t & 4095;
    int c = (t >> 12) & 63;
    int b = (t >> 18) & 1;
    float o[2];
    #pragma unroll
    for (int kind = 0; kind < 2; kind++) {
        long mb = (((long)kind * 2 + b) * NSP) * HW;
        float m0 = g_pm[mb + i], m1 = g_pm[mb + HW + i];
        float l0 = g_pl[mb + i], l1 = g_pl[mb + HW + i];
        float m = fmaxf(m0, m1);
        float w0 = exp2f(m0 - m), w1 = exp2f(m1 - m);
        float inv = 1.f / (w0 * l0 + w1 * l1);
        long ob = ((((long)kind * BATCH + b) * NSP) * CH + c) * HW + i;
        o[kind] = (w0 * g_pO[ob] + w1 * g_pO[ob + (long)CH * HW]) * inv;
    }
    int di = (b * CH + c) * HW + i;
    g_gout[di] = o[1];
    g_outb[di] = gamma[0] * o[0] + alpha[0] * o[1];
}

// ---------------- 6. plain conv3x3: 4 oc, 2 px/thread, optional fused final ----------------
__global__ void __launch_bounds__(256) kconv3(const float* __restrict__ w,
                                              const float* __restrict__ bias,
                                              int in_id, int out_id, int leaky_in,
                                              int finalize, float* __restrict__ dout) {
    const float* inb = pick_in(in_id);
    int b = blockIdx.z, ocg = blockIdx.y;

    __shared__ float ws[4 * 576];
    for (int i = threadIdx.x; i < 4 * 576; i += 256) {
        int o = i / 576, r = i % 576;
        ws[o * 576 + r] = w[(ocg * 4 + o) * 576 + r];
    }
    __syncthreads();

    int p = blockIdx.x * 512 + threadIdx.x * 2;
    int row = p >> 6, col0 = p & 63;
    float acc[4][2];
    #pragma unroll
    for (int o = 0; o < 4; o++) {
        float bv = bias[ocg * 4 + o];
        acc[o][0] = bv; acc[o][1] = bv;
    }
    const float* in = inb + b * CH * HW;

    for (int ic = 0; ic < 64; ic++) {
        const float* ch = in + ic * HW;
        #pragma unroll
        for (int kh = 0; kh < 3; kh++) {
            int hh = row + kh - 1;
            if ((unsigned)hh >= 64u) continue;
            float v[4];
            #pragma unroll
            for (int u = 0; u < 4; u++) {
                int cc = col0 - 1 + u;
                float val = ((unsigned)cc < 64u) ? ch[hh * 64 + cc] : 0.f;
                if (leaky_in) val = val > 0.f ? val : 0.1f * val;
                v[u] = val;
            }
            #pragma unroll
            for (int o = 0; o < 4; o++) {
                const float* wr = &ws[o * 576 + ic * 9 + kh * 3];
                #pragma unroll
                for (int kw = 0; kw < 3; kw++) {
                    float wv = wr[kw];
                    acc[o][0] += wv * v[kw + 0];
                    acc[o][1] += wv * v[kw + 1];
                }
            }
        }
    }
    if (finalize) {
        #pragma unroll
        for (int o = 0; o < 4; o++) {
            int base = (b * CH + ocg * 4 + o) * HW + p;
            float2 scv = *(const float2*)(g_sc + base);
            float2 gov = *(const float2*)(g_gout + base);
            *(float2*)(dout + base) = make_float2(acc[o][0] + scv.x * gov.x,
                                                  acc[o][1] + scv.y * gov.y);
        }
    } else {
        float* outb = pick_out(out_id);
        #pragma unroll
        for (int o = 0; o < 4; o++) {
            float* op = outb + (b * CH + ocg * 4 + o) * HW + p;
            *(float2*)op = make_float2(acc[o][0], acc[o][1]);
        }
    }
}

// ---------------- 3b. 1x1 conv (shortcut path) ----------------
__global__ void k1x1(const float* __restrict__ w, const float* __restrict__ bias,
                     int in_id, int out_id) {
    const float* in = pick_in(in_id);
    float* out = pick_out(out_id);
    int b = blockIdx.z, og = blockIdx.y;
    int n0 = blockIdx.x * 128;

    __shared__ float si[64 * 128];
    __shared__ float sw[8 * 64];
    for (int i = threadIdx.x; i < 64 * 128; i += 128) {
        int c = i >> 7, px = i & 127;
        si[i] = in[(b * CH + c) * HW + n0 + px];
    }
    for (int i = threadIdx.x; i < 512; i += 128)
        sw[i] = w[(og * 8 + (i >> 6)) * 64 + (i & 63)];
    __syncthreads();

    float acc[8];
    #pragma unroll
    for (int o = 0; o < 8; o++) acc[o] = bias[og * 8 + o];
    for (int c = 0; c < 64; c++) {
        float iv = si[c * 128 + threadIdx.x];
        #pragma unroll
        for (int o = 0; o < 8; o++) acc[o] += sw[o * 64 + c] * iv;
    }
    #pragma unroll
    for (int o = 0; o < 8; o++)
        out[(b * CH + og * 8 + o) * HW + n0 + threadIdx.x] = acc[o];
}

extern "C" void kernel_launch(void* const* d_in, const int* in_sizes, int n_in,
                              void* d_out, int out_size) {
    const float* x       = (const float*)d_in[0];
    const float* guide   = (const float*)d_in[1];
    const float* lin_w   = (const float*)d_in[2];
    const float* lin_b   = (const float*)d_in[3];
    const float* coord_w = (const float*)d_in[4];
    const float* xq_w = (const float*)d_in[5];
    const float* xq_b = (const float*)d_in[6];
    const float* xk_w = (const float*)d_in[7];
    const float* xk_b = (const float*)d_in[8];
    const float* xv_w = (const float*)d_in[9];
    const float* xv_b = (const float*)d_in[10];
    const float* gq_w = (const float*)d_in[11];
    const float* gq_b = (const float*)d_in[12];
    const float* gk_w = (const float*)d_in[13];
    const float* gk_b = (const float*)d_in[14];
    const float* gamma = (const float*)d_in[15];
    const float* alpha = (const float*)d_in[16];
    const float* c1_w = (const float*)d_in[17];
    const float* c1_b = (const float*)d_in[18];
    const float* c2_w = (const float*)d_in[19];
    const float* c2_b = (const float*)d_in[20];
    const float* sc_w = (const float*)d_in[21];
    const float* sc_b = (const float*)d_in[22];
    float* out = (float*)d_out;

    cudaFuncSetAttribute(kattn, cudaFuncAttributeMaxDynamicSharedMemorySize, 65536);

    kstats<<<256, 256>>>(x, guide, lin_w, lin_b);
    kgated<<<dim3(8, 16, 4), 256>>>(x, guide, coord_w);

    kproj<<<dim3(32, 8, 4), 128>>>(xq_w, xq_b, xk_w, xk_b, xv_w, xv_b,
                                   gq_w, gq_b, gk_w, gk_b);

    kattn<<<dim3(32 * NSP, BATCH, 2), 256, 65536>>>();
    kmergec<<<2048, 256>>>(gamma, alpha);

    kconv3<<<dim3(8, 16, BATCH), 256>>>(c1_w, c1_b, BUF_OUT, BUF_OT1, 1, 0, nullptr);
    k1x1<<<dim3(32, 8, BATCH), 128>>>(sc_w, sc_b, BUF_OUT, BUF_SC);
    kconv3<<<dim3(8, 16, BATCH), 256>>>(c2_w, c2_b, BUF_T1, 0, 1, 1, out);
}

// round 16
// speedup vs baseline: 1.1558x; 1.1420x over previous
#include <cuda_runtime.h>
#include <cuda_bf16.h>
#include <cstdint>

#define BATCH 2
#define CH 64
#define HW 4096   // 64*64
#define NSP 2     // KV splits
#define LOG2E 1.4426950408889634f

typedef unsigned long long u64;

__device__ __forceinline__ u64 pk2(float lo, float hi) {
    u64 r; asm("mov.b64 %0,{%1,%2};" : "=l"(r) : "f"(lo), "f"(hi)); return r;
}
__device__ __forceinline__ void upk2(u64 v, float& lo, float& hi) {
    asm("mov.b64 {%0,%1},%2;" : "=f"(lo), "=f"(hi) : "l"(v));
}
__device__ __forceinline__ u64 ffma2(u64 a, u64 b, u64 c) {
    u64 d; asm("fma.rn.f32x2 %0,%1,%2,%3;" : "=l"(d) : "l"(a), "l"(b), "l"(c)); return d;
}

// ---------------- scratch ----------------
__device__ float g_scale[4 * CH];
__device__ float g_xg[BATCH * CH * HW];
__device__ float g_gg[BATCH * CH * HW];
__device__ float g_xq[BATCH * CH * HW];
__device__ float g_gq[BATCH * CH * HW];
__device__ float g_gout[BATCH * CH * HW];
__device__ float g_outb[BATCH * CH * HW];
__device__ float g_t1[BATCH * CH * HW];
__device__ float g_sc[BATCH * CH * HW];
__device__ __nv_bfloat16 g_bkh[2 * BATCH * CH * HW];
__device__ __nv_bfloat16 g_bkl[2 * BATCH * CH * HW];
__device__ __nv_bfloat16 g_bvh[BATCH * CH * HW];
__device__ __nv_bfloat16 g_bvl[BATCH * CH * HW];
// split-KV partials
__device__ float g_pO[2 * BATCH * NSP * CH * HW];
__device__ float g_pm[2 * BATCH * NSP * HW];
__device__ float g_pl[2 * BATCH * NSP * HW];

#define BUF_XG 0
#define BUF_GG 1
#define BUF_OUT 2
#define BUF_T1 3

#define BUF_SC 5
#define BUF_OT1 6

__device__ __forceinline__ float* pick_in(int w) {
    switch (w) {
        case BUF_XG: return g_xg;
        case BUF_GG: return g_gg;
        case BUF_OUT: return g_outb;
        default:     return g_t1;
    }
}
__device__ __forceinline__ float* pick_out(int w) {
    switch (w) {
        case BUF_SC: return g_sc;
        default:     return g_t1;
    }
}

// ================= helpers =================
__device__ __forceinline__ uint32_t su32(const void* p) {
    uint32_t a;
    asm("{ .reg .u64 t; cvta.to.shared.u64 t, %1; cvt.u32.u64 %0, t; }" : "=r"(a) : "l"(p));
    return a;
}
__device__ __forceinline__ void mma_bf16(float* d, const uint32_t* a, uint32_t b0, uint32_t b1) {
    asm volatile(
        "mma.sync.aligned.m16n8k16.row.col.f32.bf16.bf16.f32 "
        "{%0,%1,%2,%3}, {%4,%5,%6,%7}, {%8,%9}, {%0,%1,%2,%3};"
        : "+f"(d[0]), "+f"(d[1]), "+f"(d[2]), "+f"(d[3])
        : "r"(a[0]), "r"(a[1]), "r"(a[2]), "r"(a[3]), "r"(b0), "r"(b1));
}
__device__ __forceinline__ void ldsm4(uint32_t* r, uint32_t addr) {
    asm volatile("ldmatrix.sync.aligned.m8n8.x4.shared.b16 {%0,%1,%2,%3}, [%4];"
                 : "=r"(r[0]), "=r"(r[1]), "=r"(r[2]), "=r"(r[3]) : "r"(addr));
}
__device__ __forceinline__ void ldsm4t(uint32_t* r, uint32_t addr) {
    asm volatile("ldmatrix.sync.aligned.m8n8.x4.trans.shared.b16 {%0,%1,%2,%3}, [%4];"
                 : "=r"(r[0]), "=r"(r[1]), "=r"(r[2]), "=r"(r[3]) : "r"(addr));
}
__device__ __forceinline__ uint32_t cvt_bf2(float lo, float hi) {
    uint32_t r;
    asm("cvt.rn.bf16x2.f32 %0, %1, %2;" : "=r"(r) : "f"(hi), "f"(lo));
    return r;
}
__device__ __forceinline__ void split2(float a, float b, uint32_t& hw, uint32_t& lw) {
    uint32_t h = cvt_bf2(a, b);
    float ra = a - __uint_as_float(h << 16);
    float rb = b - __uint_as_float(h & 0xFFFF0000u);
    hw = h;
    lw = cvt_bf2(ra, rb);
}
__device__ __forceinline__ void wrb(__nv_bfloat16* H, __nv_bfloat16* L, int idx, float v) {
    __nv_bfloat16 h = __float2bfloat16_rn(v);
    H[idx] = h;
    L[idx] = __float2bfloat16_rn(v - __bfloat162float(h));
}
__device__ __forceinline__ void cpa16(uint32_t dst, const void* src) {
    asm volatile("cp.async.cg.shared.global [%0], [%1], 16;" :: "r"(dst), "l"(src) : "memory");
}
#define CPA_COMMIT() asm volatile("cp.async.commit_group;" ::: "memory")
#define CPA_WAIT1()  asm volatile("cp.async.wait_group 1;" ::: "memory")
#define CPA_WAIT0()  asm volatile("cp.async.wait_group 0;" ::: "memory")

// ---------------- 1. channel attention scalars ----------------
__global__ void kstats(const float* __restrict__ x, const float* __restrict__ g,
                       const float* __restrict__ lw, const float* __restrict__ lb) {
    int idx = blockIdx.x;
    int t = idx >> 7, b = (idx >> 6) & 1, c = idx & 63;
    const float* in = (t ? g : x) + (b * CH + c) * HW;
    float s = 0.f;
    for (int i = threadIdx.x; i < HW; i += 256) s += in[i];
    __shared__ float red[8];
    #pragma unroll
    for (int o = 16; o > 0; o >>= 1) s += __shfl_xor_sync(0xffffffffu, s, o);
    if ((threadIdx.x & 31) == 0) red[threadIdx.x >> 5] = s;
    __syncthreads();
    if (threadIdx.x == 0) {
        float tot = 0.f;
        #pragma unroll
        for (int i = 0; i < 8; i++) tot += red[i];
        float p = tot * (1.0f / (float)HW);
        float W = lw[0], B = lb[0];
        float h = p * W + B;
        h = h > 0.f ? h : 0.1f * h;
        float z = h * W + B;
        g_scale[idx] = 1.f / (1.f + expf(-z));
    }
}

// ---------------- 2. gated coord conv: 4 oc, 2 px/thread, 512 CTAs ----------------
__global__ void __launch_bounds__(256) kgated(const float* __restrict__ xin,
                                              const float* __restrict__ gin,
                                              const float* __restrict__ cw) {
    int z = blockIdx.z;
    int t = z >> 1, b = z & 1;
    const float* in = (t ? gin : xin) + b * CH * HW;
    float* out = (t ? g_gg : g_xg) + b * CH * HW;
    int ocg = blockIdx.y;

    __shared__ float ws[4 * 66 * 9];
    for (int i = threadIdx.x; i < 4 * 594; i += 256) {
        int o = i / 594, r = i % 594;
        ws[o * 594 + r] = cw[(ocg * 4 + o) * 594 + r];
    }
    __syncthreads();

    int p = blockIdx.x * 512 + threadIdx.x * 2;
    int row = p >> 6, col0 = p & 63;
    float acc[4][2];
    #pragma unroll
    for (int o = 0; o < 4; o++) { acc[o][0] = 0.f; acc[o][1] = 0.f; }

    for (int ic = 0; ic < 64; ic++) {
        const float* ch = in + ic * HW;
        #pragma unroll
        for (int kh = 0; kh < 3; kh++) {
            int hh = row + kh - 1;
            if ((unsigned)hh >= 64u) continue;
            float v[4];
            #pragma unroll
            for (int u = 0; u < 4; u++) {
                int cc = col0 - 1 + u;
                v[u] = ((unsigned)cc < 64u) ? ch[hh * 64 + cc] : 0.f;
            }
            #pragma unroll
            for (int o = 0; o < 4; o++) {
                const float* wr = &ws[o * 594 + ic * 9 + kh * 3];
                #pragma unroll
                for (int kw = 0; kw < 3; kw++) {
                    float wv = wr[kw];
                    acc[o][0] += wv * v[kw + 0];
                    acc[o][1] += wv * v[kw + 1];
                }
            }
        }
    }
    #pragma unroll
    for (int ic = 64; ic < 66; ic++) {
        #pragma unroll
        for (int kh = 0; kh < 3; kh++) {
            int hh = row + kh - 1;
            if ((unsigned)hh >= 64u) continue;
            float yyv = (float)hh * (2.f / 63.f) - 1.f;
            float v[4];
            #pragma unroll
            for (int u = 0; u < 4; u++) {
                int cc = col0 - 1 + u;
                float val = 0.f;
                if ((unsigned)cc < 64u)
                    val = (ic == 64) ? ((float)cc * (2.f / 63.f) - 1.f) : yyv;
                v[u] = val;
            }
            #pragma unroll
            for (int o = 0; o < 4; o++) {
                const float* wr = &ws[o * 594 + ic * 9 + kh * 3];
                #pragma unroll
                for (int kw = 0; kw < 3; kw++) {
                    float wv = wr[kw];
                    acc[o][0] += wv * v[kw + 0];
                    acc[o][1] += wv * v[kw + 1];
                }
            }
        }
    }

    #pragma unroll
    for (int o = 0; o < 4; o++) {
        int oc = ocg * 4 + o;
        float s = g_scale[z * CH + oc];
        *(float2*)(out + oc * HW + p) = make_float2(s * acc[o][0], s * acc[o][1]);
    }
}

// ---------------- 3. fused QKV projections; K/V written as bf16 hi/lo ----------------
__global__ void __launch_bounds__(128) kproj(
    const float* __restrict__ xq_w, const float* __restrict__ xq_b,
    const float* __restrict__ xk_w, const float* __restrict__ xk_b,
    const float* __restrict__ xv_w, const float* __restrict__ xv_b,
    const float* __restrict__ gq_w, const float* __restrict__ gq_b,
    const float* __restrict__ gk_w, const float* __restrict__ gk_b) {
    __shared__ float si[64 * 128];
    __shared__ float swt[3 * 512];
    __shared__ float sb2[3 * 8];

    int z = blockIdx.z;
    int side = z >> 1, b = z & 1;
    int og = blockIdx.y;
    int n0 = blockIdx.x * 128;
    int tid = threadIdx.x;

    const float* in = (side ? g_gg : g_xg) + b * CH * HW;
    const float* ws[3];
    const float* bs[3];
    int nset;
    if (side == 0) {
        ws[0] = xq_w; ws[1] = xk_w; ws[2] = xv_w;
        bs[0] = xq_b; bs[1] = xk_b; bs[2] = xv_b;
        nset = 3;
    } else {
        ws[0] = gq_w; ws[1] = gk_w; ws[2] = gk_w;
        bs[0] = gq_b; bs[1] = gk_b; bs[2] = gk_b;
        nset = 2;
    }

    for (int i = tid; i < 2048; i += 128) {
        int c = i >> 5, p4 = (i & 31) * 4;
        *(float4*)(si + c * 128 + p4) = *(const float4*)(in + c * HW + n0 + p4);
    }
    for (int s = 0; s < nset; s++) {
        for (int i = tid; i < 512; i += 128) {
            int c = i >> 3, o = i & 7;
            swt[s * 512 + c * 8 + o] = ws[s][(og * 8 + o) * 64 + c];
        }
        if (tid < 8) sb2[s * 8 + tid] = bs[s][og * 8 + tid];
    }
    __syncthreads();

    u64 acc[3][4];
    #pragma unroll
    for (int s = 0; s < 3; s++)
        #pragma unroll
        for (int k = 0; k < 4; k++)
            acc[s][k] = pk2(sb2[s * 8 + 2 * k], sb2[s * 8 + 2 * k + 1]);

    if (side == 0) {
        for (int c = 0; c < 64; c++) {
            float iv = si[c * 128 + tid];
            u64 ivp = pk2(iv, iv);
            #pragma unroll
            for (int s = 0; s < 3; s++) {
                ulonglong2 wa = *(const ulonglong2*)(swt + s * 512 + c * 8);
                ulonglong2 wb = *(const ulonglong2*)(swt + s * 512 + c * 8 + 4);
                acc[s][0] = ffma2(ivp, wa.x, acc[s][0]);
                acc[s][1] = ffma2(ivp, wa.y, acc[s][1]);
                acc[s][2] = ffma2(ivp, wb.x, acc[s][2]);
                acc[s][3] = ffma2(ivp, wb.y, acc[s][3]);
            }
        }
    } else {
        for (int c = 0; c < 64; c++) {
            float iv = si[c * 128 + tid];
            u64 ivp = pk2(iv, iv);
            #pragma unroll
            for (int s = 0; s < 2; s++) {
                ulonglong2 wa = *(const ulonglong2*)(swt + s * 512 + c * 8);
                ulonglong2 wb = *(const ulonglong2*)(swt + s * 512 + c * 8 + 4);
                acc[s][0] = ffma2(ivp, wa.x, acc[s][0]);
                acc[s][1] = ffma2(ivp, wa.y, acc[s][1]);
                acc[s][2] = ffma2(ivp, wb.x, acc[s][2]);
                acc[s][3] = ffma2(ivp, wb.y, acc[s][3]);
            }
        }
    }

    float* qdst = side ? g_gq : g_xq;
    __nv_bfloat16* KhD = g_bkh + (long)side * BATCH * CH * HW;
    __nv_bfloat16* KlD = g_bkl + (long)side * BATCH * CH * HW;
    #pragma unroll
    for (int k = 0; k < 4; k++) {
        int i0 = (b * CH + og * 8 + 2 * k) * HW + n0 + tid;
        float lo, hi;
        upk2(acc[0][k], lo, hi);
        qdst[i0] = lo; qdst[i0 + HW] = hi;
        upk2(acc[1][k], lo, hi);
        wrb(KhD, KlD, i0, lo); wrb(KhD, KlD, i0 + HW, hi);
        if (side == 0) {
            upk2(acc[2][k], lo, hi);
            wrb(g_bvh, g_bvl, i0, lo); wrb(g_bvh, g_bvl, i0 + HW, hi);
        }
    }
}

// ---------------- 4. flash attention: split-KV, 256 threads, double-buffered, 1 wave ----------------
__global__ void __launch_bounds__(256, 2) kattn() {
    extern __shared__ __align__(16) uint8_t dyn[];

    const int tid = threadIdx.x;
    const int lane = tid & 31, wid = tid >> 5;
    const int tg = lane & 3, g = lane >> 2;
    const int b = blockIdx.y, kind = blockIdx.z;
    const int nt = blockIdx.x >> 1, sp = blockIdx.x & 1;
    const int n0 = nt * 128;
    const int kt0 = sp * 32;
    const float* Qp = (kind ? g_gq : g_xq) + b * CH * HW;
    const __nv_bfloat16* Kh = g_bkh + ((long)kind * BATCH + b) * CH * HW;
    const __nv_bfloat16* Kl = g_bkl + ((long)kind * BATCH + b) * CH * HW;
    const __nv_bfloat16* Vh = g_bvh + (long)b * CH * HW;
    const __nv_bfloat16* Vl = g_bvl + (long)b * CH * HW;

    const uint32_t sb = su32(dyn);

    for (int idx = tid; idx < 8192; idx += 256) {
        int i = idx & 127, c = idx >> 7;
        float a = Qp[c * HW + n0 + i] * LOG2E;
        __nv_bfloat16 h = __float2bfloat16_rn(a);
        uint32_t off = (uint32_t)(i * 128 + ((((c >> 3) ^ (i & 7))) << 4) + (c & 7) * 2);
        *(__nv_bfloat16*)(dyn + off) = h;
        *(__nv_bfloat16*)(dyn + 16384 + off) = __float2bfloat16_rn(a - __bfloat162float(h));
    }
    __syncthreads();

    const int rl = lane & 15, hi_half = lane >> 4, r7 = rl & 7;
    uint32_t qh[4][4], ql[4][4];
    #pragma unroll
    for (int kc = 0; kc < 4; kc++) {
        uint32_t off = (uint32_t)((16 * wid + rl) * 128 + (((kc * 2 + hi_half) ^ r7) << 4));
        ldsm4(qh[kc], sb + off);
        ldsm4(ql[kc], sb + 16384 + off);
    }
    __syncthreads();

    float oacc[8][4];
    #pragma unroll
    for (int cb = 0; cb < 8; cb++) {
        oacc[cb][0] = 0.f; oacc[cb][1] = 0.f; oacc[cb][2] = 0.f; oacc[cb][3] = 0.f;
    }
    float mrow0 = -1e30f, mrow1 = -1e30f, lrow0 = 0.f, lrow1 = 0.f;

    const int vrow = ((lane >> 4) << 3) + (lane & 7);
    const int vch = (lane >> 3) & 1;
    const int v7 = lane & 7;

    {
        int m0 = kt0 * 64;
        #pragma unroll
        for (int u = 0; u < 2; u++) {
            int i = tid + u * 256;
            int row = i >> 3, ch = i & 7;
            uint32_t dst = sb + row * 128 + (((ch ^ (row & 7))) << 4);
            long go = (long)row * HW + m0 + ch * 8;
            cpa16(dst,          Kh + go);
            cpa16(dst + 8192,   Kl + go);
            cpa16(dst + 16384,  Vh + go);
            cpa16(dst + 24576,  Vl + go);
        }
        CPA_COMMIT();
    }

    for (int kt = 0; kt < 32; kt++) {
        const uint32_t bufc = sb + (uint32_t)(kt & 1) * 32768;

        if (kt < 31) {
            uint32_t bufn = sb + (uint32_t)((kt + 1) & 1) * 32768;
            int m0n = (kt0 + kt + 1) * 64;
            #pragma unroll
            for (int u = 0; u < 2; u++) {
                int i = tid + u * 256;
                int row = i >> 3, ch = i & 7;
                uint32_t dst = bufn + row * 128 + (((ch ^ (row & 7))) << 4);
                long go = (long)row * HW + m0n + ch * 8;
                cpa16(dst,          Kh + go);
                cpa16(dst + 8192,   Kl + go);
                cpa16(dst + 16384,  Vh + go);
                cpa16(dst + 24576,  Vl + go);
            }
            CPA_COMMIT();
            CPA_WAIT1();
        } else {
            CPA_WAIT0();
        }
        __syncthreads();

        float sa[8][4];
        #pragma unroll
        for (int nb = 0; nb < 8; nb++) {
            sa[nb][0] = 0.f; sa[nb][1] = 0.f; sa[nb][2] = 0.f; sa[nb][3] = 0.f;
        }
        #pragma unroll
        for (int kc = 0; kc < 4; kc++) {
            #pragma unroll
            for (int jb = 0; jb < 4; jb++) {
                uint32_t bh[4], bl[4];
                uint32_t koff = (uint32_t)((kc * 16 + rl) * 128 +
                                           (((jb * 2 + hi_half) ^ r7) << 4));
                ldsm4t(bh, bufc + koff);
                ldsm4t(bl, bufc + 8192 + koff);
                mma_bf16(sa[2 * jb],     qh[kc], bh[0], bh[1]);
                mma_bf16(sa[2 * jb],     qh[kc], bl[0], bl[1]);
                mma_bf16(sa[2 * jb],     ql[kc], bh[0], bh[1]);
                mma_bf16(sa[2 * jb + 1], qh[kc], bh[2], bh[3]);
                mma_bf16(sa[2 * jb + 1], qh[kc], bl[2], bl[3]);
                mma_bf16(sa[2 * jb + 1], ql[kc], bh[2], bh[3]);
            }
        }

        float tm0 = -1e30f, tm1 = -1e30f;
        #pragma unroll
        for (int nb = 0; nb < 8; nb++) {
            tm0 = fmaxf(tm0, fmaxf(sa[nb][0], sa[nb][1]));
            tm1 = fmaxf(tm1, fmaxf(sa[nb][2], sa[nb][3]));
        }
        tm0 = fmaxf(tm0, __shfl_xor_sync(0xffffffffu, tm0, 1));
        tm0 = fmaxf(tm0, __shfl_xor_sync(0xffffffffu, tm0, 2));
        tm1 = fmaxf(tm1, __shfl_xor_sync(0xffffffffu, tm1, 1));
        tm1 = fmaxf(tm1, __shfl_xor_sync(0xffffffffu, tm1, 2));
        float mn0 = fmaxf(mrow0, tm0), mn1 = fmaxf(mrow1, tm1);
        float corr0 = exp2f(mrow0 - mn0), corr1 = exp2f(mrow1 - mn1);
        mrow0 = mn0; mrow1 = mn1;

        float ps0 = 0.f, ps1 = 0.f;
        #pragma unroll
        for (int nb = 0; nb < 8; nb++) {
            sa[nb][0] = exp2f(sa[nb][0] - mn0);
            sa[nb][1] = exp2f(sa[nb][1] - mn0);
            sa[nb][2] = exp2f(sa[nb][2] - mn1);
            sa[nb][3] = exp2f(sa[nb][3] - mn1);
            ps0 += sa[nb][0] + sa[nb][1];
            ps1 += sa[nb][2] + sa[nb][3];
        }
        ps0 += __shfl_xor_sync(0xffffffffu, ps0, 1);
        ps0 += __shfl_xor_sync(0xffffffffu, ps0, 2);
        ps1 += __shfl_xor_sync(0xffffffffu, ps1, 1);
        ps1 += __shfl_xor_sync(0xffffffffu, ps1, 2);
        lrow0 = lrow0 * corr0 + ps0;
        lrow1 = lrow1 * corr1 + ps1;

        #pragma unroll
        for (int cb = 0; cb < 8; cb++) {
            oacc[cb][0] *= corr0; oacc[cb][1] *= corr0;
            oacc[cb][2] *= corr1; oacc[cb][3] *= corr1;
        }

        uint32_t ph[4][4], pl[4][4];
        #pragma unroll
        for (int kc = 0; kc < 4; kc++) {
            split2(sa[2 * kc][0],     sa[2 * kc][1],     ph[kc][0], pl[kc][0]);
            split2(sa[2 * kc][2],     sa[2 * kc][3],     ph[kc][1], pl[kc][1]);
            split2(sa[2 * kc + 1][0], sa[2 * kc + 1][1], ph[kc][2], pl[kc][2]);
            split2(sa[2 * kc + 1][2], sa[2 * kc + 1][3], ph[kc][3], pl[kc][3]);
        }

        #pragma unroll
        for (int kc = 0; kc < 4; kc++) {
            #pragma unroll
            for (int cp = 0; cp < 4; cp++) {
                uint32_t bh[4], bl[4];
                uint32_t voff = (uint32_t)((cp * 16 + vrow) * 128 +
                                           (((kc * 2 + vch) ^ v7) << 4));
                ldsm4(bh, bufc + 16384 + voff);
                ldsm4(bl, bufc + 24576 + voff);
                mma_bf16(oacc[2 * cp],     ph[kc], bh[0], bh[1]);
                mma_bf16(oacc[2 * cp],     ph[kc], bl[0], bl[1]);
                mma_bf16(oacc[2 * cp],     pl[kc], bh[0], bh[1]);
                mma_bf16(oacc[2 * cp + 1], ph[kc], bh[2], bh[3]);
                mma_bf16(oacc[2 * cp + 1], ph[kc], bl[2], bl[3]);
                mma_bf16(oacc[2 * cp + 1], pl[kc], bh[2], bh[3]);
            }
        }
        __syncthreads();
    }

    long pbase = ((((long)kind * BATCH + b) * NSP + sp) * CH) * HW;
    int i0 = n0 + 16 * wid + g;
    #pragma unroll
    for (int cb = 0; cb < 8; cb++) {
        int c = 8 * cb + 2 * tg;
        g_pO[pbase + (long)c * HW + i0]           = oacc[cb][0];
        g_pO[pbase + (long)(c + 1) * HW + i0]     = oacc[cb][1];
        g_pO[pbase + (long)c * HW + i0 + 8]       = oacc[cb][2];
        g_pO[pbase + (long)(c + 1) * HW + i0 + 8] = oacc[cb][3];
    }
    if (tg == 0) {
        long mb = (((long)kind * 2 + b) * NSP + sp) * HW;
        g_pm[mb + i0] = mrow0;     g_pl[mb + i0] = lrow0;
        g_pm[mb + i0 + 8] = mrow1; g_pl[mb + i0 + 8] = lrow1;
    }
}

// ---------------- 4b. merge 2 splits + combine (gamma/alpha) fused ----------------
__global__ void kmergec(const float* __restrict__ gamma, const float* __restrict__ alpha) {
    int t = blockIdx.x * 256 + threadIdx.x;
    int i = t & 4095;
    int c = (t >> 12) & 63;
    int b = (t >> 18) & 1;
    float o[2];
    #pragma unroll
    for (int kind = 0; kind < 2; kind++) {
        long mb = (((long)kind * 2 + b) * NSP) * HW;
        float m0 = g_pm[mb + i], m1 = g_pm[mb + HW + i];
        float l0 = g_pl[mb + i], l1 = g_pl[mb + HW + i];
        float m = fmaxf(m0, m1);
        float w0 = exp2f(m0 - m), w1 = exp2f(m1 - m);
        float inv = 1.f / (w0 * l0 + w1 * l1);
        long ob = ((((long)kind * BATCH + b) * NSP) * CH + c) * HW + i;
        o[kind] = (w0 * g_pO[ob] + w1 * g_pO[ob + (long)CH * HW]) * inv;
    }
    int di = (b * CH + c) * HW + i;
    g_gout[di] = o[1];
    g_outb[di] = gamma[0] * o[0] + alpha[0] * o[1];
}

// ---------------- 6. tensor-core conv3x3 (implicit GEMM, hi/lo bf16) ----------------
// grid (128, BATCH): x = r*2 + half. block 256 = 8 warps (4 oc-warps x 2 px-warps).
// CTA: 64 oc x 32 px (one half image row). B tile: [102 px-pad][64 ic] hi/lo, 144B rows.
// A tile per tap: [64 oc][64 ic] hi/lo, 144B rows. Tap shift = B row-base offset.
__global__ void __launch_bounds__(256) kconv3t(const float* __restrict__ w,
                                               const float* __restrict__ bias,
                                               int in_id, int out_id, int leaky_in,
                                               int finalize, float* __restrict__ dout) {
    __shared__ __align__(16) uint8_t smem[47808];
    // Bh [0,14688) Bl [14688,29376) Ah [29376,38592) Al [38592,47808)
    const int tid = threadIdx.x;
    const int lane = tid & 31, wid = tid >> 5;
    const int wo = wid >> 1, wp = wid & 1;
    const int r = blockIdx.x >> 1, half = blockIdx.x & 1;
    const int b = blockIdx.y;
    const int c_base = half * 32;
    const float* in = pick_in(in_id) + b * CH * HW;
    const uint32_t sB = su32(smem);

    // ---- stage B: padded pixel coords, rows = lr*34 + (c - c_base) + 1, lr = 0..2 ----
    for (int idx = tid; idx < 102 * 64; idx += 256) {
        int row = idx >> 6, ic = idx & 63;
        int lr = row / 34, tc = row - lr * 34;
        int ir = r + lr - 1, cc = c_base + tc - 1;
        float v = 0.f;
        if ((unsigned)ir < 64u && (unsigned)cc < 64u) {
            v = in[ic * HW + ir * 64 + cc];
            if (leaky_in) v = v > 0.f ? v : 0.1f * v;
        }
        __nv_bfloat16 h = __float2bfloat16_rn(v);
        *(__nv_bfloat16*)(smem + row * 144 + ic * 2) = h;
        *(__nv_bfloat16*)(smem + 14688 + row * 144 + ic * 2) =
            __float2bfloat16_rn(v - __bfloat162float(h));
    }

    const int g = lane >> 2, t2 = (lane & 3) * 2;
    float acc[2][4];
    {
        float b0v = bias[wo * 16 + g], b1v = bias[wo * 16 + 8 + g];
        acc[0][0] = b0v; acc[0][1] = b0v; acc[0][2] = b1v; acc[0][3] = b1v;
        acc[1][0] = b0v; acc[1][1] = b0v; acc[1][2] = b1v; acc[1][3] = b1v;
    }

    const uint32_t aoff = (uint32_t)(29376 + (wo * 16 + (lane & 15)) * 144 + ((lane >> 4) << 4));
    const uint32_t boff = (uint32_t)(((((lane >> 4) << 3) + (lane & 7))) * 144 +
                                     (((lane >> 3) & 1) << 4));

    for (int tap = 0; tap < 9; tap++) {
        __syncthreads();
        // stage A for this tap: w[oc][ic][tap]
        for (int idx = tid; idx < 4096; idx += 256) {
            int oc = idx >> 6, ic = idx & 63;
            float v = w[(oc * 64 + ic) * 9 + tap];
            __nv_bfloat16 h = __float2bfloat16_rn(v);
            *(__nv_bfloat16*)(smem + 29376 + oc * 144 + ic * 2) = h;
            *(__nv_bfloat16*)(smem + 38592 + oc * 144 + ic * 2) =
                __float2bfloat16_rn(v - __bfloat162float(h));
        }
        __syncthreads();

        int kh = tap / 3, kw = tap - kh * 3;
        uint32_t brow = (uint32_t)((kh * 34 + kw + wp * 16) * 144);
        #pragma unroll
        for (int icc = 0; icc < 4; icc++) {
            uint32_t ha[4], la[4], hb[4], lb[4];
            ldsm4(ha, sB + aoff + icc * 32);
            ldsm4(la, sB + aoff + 9216 + icc * 32);
            ldsm4(hb, sB + brow + boff + icc * 32);
            ldsm4(lb, sB + 14688 + brow + boff + icc * 32);
            mma_bf16(acc[0], ha, hb[0], hb[1]);
            mma_bf16(acc[1], ha, hb[2], hb[3]);
            mma_bf16(acc[0], ha, lb[0], lb[1]);
            mma_bf16(acc[1], ha, lb[2], lb[3]);
            mma_bf16(acc[0], la, hb[0], hb[1]);
            mma_bf16(acc[1], la, hb[2], hb[3]);
        }
    }

    // ---- epilogue ----
    int oc0 = wo * 16 + g;
    #pragma unroll
    for (int nt = 0; nt < 2; nt++) {
        int px = r * 64 + c_base + wp * 16 + nt * 8 + t2;
        if (finalize) {
            int base0 = (b * CH + oc0) * HW + px;
            float2 sc2 = *(const float2*)(g_sc + base0);
            float2 go2 = *(const float2*)(g_gout + base0);
            *(float2*)(dout + base0) = make_float2(acc[nt][0] + sc2.x * go2.x,
                                                   acc[nt][1] + sc2.y * go2.y);
            int base1 = (b * CH + oc0 + 8) * HW + px;
            sc2 = *(const float2*)(g_sc + base1);
            go2 = *(const float2*)(g_gout + base1);
            *(float2*)(dout + base1) = make_float2(acc[nt][2] + sc2.x * go2.x,
                                                   acc[nt][3] + sc2.y * go2.y);
        } else {
            float* outb = pick_out(out_id);
            *(float2*)(outb + (b * CH + oc0) * HW + px) = make_float2(acc[nt][0], acc[nt][1]);
            *(float2*)(outb + (b * CH + oc0 + 8) * HW + px) = make_float2(acc[nt][2], acc[nt][3]);
        }
    }
}

// ---------------- 3b. 1x1 conv (shortcut path) ----------------
__global__ void k1x1(const float* __restrict__ w, const float* __restrict__ bias,
                     int in_id, int out_id) {
    const float* in = pick_in(in_id);
    float* out = pick_out(out_id);
    int b = blockIdx.z, og = blockIdx.y;
    int n0 = blockIdx.x * 128;

    __shared__ float si[64 * 128];
    __shared__ float sw[8 * 64];
    for (int i = threadIdx.x; i < 64 * 128; i += 128) {
        int c = i >> 7, px = i & 127;
        si[i] = in[(b * CH + c) * HW + n0 + px];
    }
    for (int i = threadIdx.x; i < 512; i += 128)
        sw[i] = w[(og * 8 + (i >> 6)) * 64 + (i & 63)];
    __syncthreads();

    float acc[8];
    #pragma unroll
    for (int o = 0; o < 8; o++) acc[o] = bias[og * 8 + o];
    for (int c = 0; c < 64; c++) {
        float iv = si[c * 128 + threadIdx.x];
        #pragma unroll
        for (int o = 0; o < 8; o++) acc[o] += sw[o * 64 + c] * iv;
    }
    #pragma unroll
    for (int o = 0; o < 8; o++)
        out[(b * CH + og * 8 + o) * HW + n0 + threadIdx.x] = acc[o];
}

extern "C" void kernel_launch(void* const* d_in, const int* in_sizes, int n_in,
                              void* d_out, int out_size) {
    const float* x       = (const float*)d_in[0];
    const float* guide   = (const float*)d_in[1];
    const float* lin_w   = (const float*)d_in[2];
    const float* lin_b   = (const float*)d_in[3];
    const float* coord_w = (const float*)d_in[4];
    const float* xq_w = (const float*)d_in[5];
    const float* xq_b = (const float*)d_in[6];
    const float* xk_w = (const float*)d_in[7];
    const float* xk_b = (const float*)d_in[8];
    const float* xv_w = (const float*)d_in[9];
    const float* xv_b = (const float*)d_in[10];
    const float* gq_w = (const float*)d_in[11];
    const float* gq_b = (const float*)d_in[12];
    const float* gk_w = (const float*)d_in[13];
    const float* gk_b = (const float*)d_in[14];
    const float* gamma = (const float*)d_in[15];
    const float* alpha = (const float*)d_in[16];
    const float* c1_w = (const float*)d_in[17];
    const float* c1_b = (const float*)d_in[18];
    const float* c2_w = (const float*)d_in[19];
    const float* c2_b = (const float*)d_in[20];
    const float* sc_w = (const float*)d_in[21];
    const float* sc_b = (const float*)d_in[22];
    float* out = (float*)d_out;

    cudaFuncSetAttribute(kattn, cudaFuncAttributeMaxDynamicSharedMemorySize, 65536);

    kstats<<<256, 256>>>(x, guide, lin_w, lin_b);
    kgated<<<dim3(8, 16, 4), 256>>>(x, guide, coord_w);

    kproj<<<dim3(32, 8, 4), 128>>>(xq_w, xq_b, xk_w, xk_b, xv_w, xv_b,
                                   gq_w, gq_b, gk_w, gk_b);

    kattn<<<dim3(32 * NSP, BATCH, 2), 256, 65536>>>();
    kmergec<<<2048, 256>>>(gamma, alpha);

    kconv3t<<<dim3(128, BATCH), 256>>>(c1_w, c1_b, BUF_OUT, BUF_OT1, 1, 0, nullptr);
    k1x1<<<dim3(32, 8, BATCH), 128>>>(sc_w, sc_b, BUF_OUT, BUF_SC);
    kconv3t<<<dim3(128, BATCH), 256>>>(c2_w, c2_b, BUF_T1, 0, 1, 1, out);
}